// round 6
// baseline (speedup 1.0000x reference)
#include <cuda_runtime.h>
#include <cuda_bf16.h>
#include <math.h>
#include <stdint.h>

#define BB 32768
#define KK 32
#define DD 256
#define HH 8
#define DKK 32
#define FFD 1024

// ---------------- scratch (static device allocations; no cudaMalloc) ----------------
__device__ float g_xln[BB * DD];            // LN1(x_anc)
__device__ float g_Q[BB * DD];              // xln @ W_q
__device__ float g_Qt[(size_t)BB * HH * DD];// per-head Q_h @ Wk_h^T (scaled 1/sqrt(dk))
__device__ float g_y[(size_t)BB * HH * DD]; // attn-weighted neighbor sums
__device__ float g_v[BB * DD];              // per-head y_h @ Wv_h (concat)
__device__ float g_x[BB * DD];              // x_anc + v @ W_o
__device__ float g_hln[BB * DD];            // LN2(x)
__device__ float g_act[(size_t)BB * FFD];   // gelu(hln @ ff1 + b1)
__device__ float g_WkT[DD * DD];            // WkT[h*32+j][d] = W_k[d][h*32+j]

// ---------------- tiny prep: transpose W_k ----------------
__global__ void prep_wkt(const float* __restrict__ Wk, float* __restrict__ WkT) {
    int i = blockIdx.x * 256 + threadIdx.x;      // 0..65535
    int d = i & 255;
    int hj = i >> 8;
    WkT[hj * 256 + d] = Wk[d * 256 + hj];
}

// ---------------- row layernorm: 1 warp per row ----------------
__global__ void __launch_bounds__(256) ln_kernel(const float* __restrict__ X,
                                                 const float* __restrict__ gam,
                                                 const float* __restrict__ bet,
                                                 float* __restrict__ Y) {
    int row = blockIdx.x * 8 + (threadIdx.x >> 5);
    int l = threadIdx.x & 31;
    const float4* xr = (const float4*)(X + (size_t)row * DD);
    float4 v0 = xr[l];
    float4 v1 = xr[l + 32];
    float s = v0.x + v0.y + v0.z + v0.w + v1.x + v1.y + v1.z + v1.w;
    float sq = v0.x * v0.x + v0.y * v0.y + v0.z * v0.z + v0.w * v0.w +
               v1.x * v1.x + v1.y * v1.y + v1.z * v1.z + v1.w * v1.w;
#pragma unroll
    for (int o = 16; o > 0; o >>= 1) {
        s += __shfl_xor_sync(0xffffffffu, s, o);
        sq += __shfl_xor_sync(0xffffffffu, sq, o);
    }
    float mu = s * (1.0f / 256.0f);
    float var = sq * (1.0f / 256.0f) - mu * mu;
    float inv = rsqrtf(var + 1e-5f);
    float4 g0 = ((const float4*)gam)[l];
    float4 g1 = ((const float4*)gam)[l + 32];
    float4 b0 = ((const float4*)bet)[l];
    float4 b1 = ((const float4*)bet)[l + 32];
    float4 o0, o1;
    o0.x = (v0.x - mu) * inv * g0.x + b0.x;
    o0.y = (v0.y - mu) * inv * g0.y + b0.y;
    o0.z = (v0.z - mu) * inv * g0.z + b0.z;
    o0.w = (v0.w - mu) * inv * g0.w + b0.w;
    o1.x = (v1.x - mu) * inv * g1.x + b1.x;
    o1.y = (v1.y - mu) * inv * g1.y + b1.y;
    o1.z = (v1.z - mu) * inv * g1.z + b1.z;
    o1.w = (v1.w - mu) * inv * g1.w + b1.w;
    float4* yr = (float4*)(Y + (size_t)row * DD);
    yr[l] = o0;
    yr[l + 32] = o1;
}

// ---------------- bf16-split tensor-core GEMM ----------------
// C = epilogue(alpha * A@B) computed as hi@hi + hi@lo + lo@hi (bf16x3 split).
// Error ~2^-16 relative — far under the 1e-3 harness threshold.
// A: MxK row-major fp32, B: KxN row-major fp32, C: MxN fp32.
// EPI 0: alpha*acc
// EPI 1: t = acc + bias[c]; t * normcdf(t)       (exact GELU)
// EPI 2: acc + bias[c] + R[r,c]
// EPI 3: acc + R[r,c]
// blockIdx.z: A += z*sA, B += z*sB, C += z*sC (per-head batching).

__device__ __forceinline__ void mma16816(float* c,
                                         uint32_t a0, uint32_t a1, uint32_t a2, uint32_t a3,
                                         uint32_t b0, uint32_t b1) {
    asm volatile(
        "mma.sync.aligned.m16n8k16.row.col.f32.bf16.bf16.f32 "
        "{%0,%1,%2,%3},{%4,%5,%6,%7},{%8,%9},{%0,%1,%2,%3};"
        : "+f"(c[0]), "+f"(c[1]), "+f"(c[2]), "+f"(c[3])
        : "r"(a0), "r"(a1), "r"(a2), "r"(a3), "r"(b0), "r"(b1));
}

__device__ __forceinline__ void split_pair(__nv_bfloat16* hp, __nv_bfloat16* lp,
                                           float a, float b) {
    __nv_bfloat16 h0 = __float2bfloat16(a);
    __nv_bfloat16 h1 = __float2bfloat16(b);
    float r0 = a - __bfloat162float(h0);
    float r1 = b - __bfloat162float(h1);
    __nv_bfloat162 hh; hh.x = h0; hh.y = h1;
    __nv_bfloat162 ll; ll.x = __float2bfloat16(r0); ll.y = __float2bfloat16(r1);
    *(__nv_bfloat162*)hp = hh;
    *(__nv_bfloat162*)lp = ll;
}

template <int BN, int WM, int WN, int EPI>
__global__ void __launch_bounds__(256) mma_gemm(
    const float* __restrict__ A, int lda, long sA,
    const float* __restrict__ Bm, int ldb, long sB,
    float* __restrict__ C, int ldc, long sC,
    int Kd, float alpha,
    const float* __restrict__ bias,
    const float* __restrict__ R, int ldr) {
    constexpr int BM = 128;
    constexpr int BK = 32;
    constexpr int LDK = 40;                  // padded K stride (halves) — conflict-free frags
    constexpr int NWN = BN / WN;
    constexpr int MT = WM / 16;
    constexpr int NT = WN / 8;
    constexpr int BNq = BN / 4;              // float4 per B k-row
    constexpr int BF4PT = (8 * BN) / 256;    // B float4 per thread per tile
    static_assert((BM / WM) * (BN / WN) == 8, "8 warps");

    __shared__ __nv_bfloat16 As_h[BM][LDK];
    __shared__ __nv_bfloat16 As_l[BM][LDK];
    __shared__ __nv_bfloat16 Bs_h[BN][LDK];
    __shared__ __nv_bfloat16 Bs_l[BN][LDK];

    A  += (size_t)blockIdx.z * sA;
    Bm += (size_t)blockIdx.z * sB;
    C  += (size_t)blockIdx.z * sC;

    const int t = threadIdx.x;
    const int w = t >> 5;
    const int lane = t & 31;
    const int g = lane >> 2;
    const int tig = lane & 3;
    const int wm = (w / NWN) * WM;
    const int wn = (w % NWN) * WN;
    const int row0 = blockIdx.y * BM;
    const int col0 = blockIdx.x * BN;

    float acc[MT][NT][4];
#pragma unroll
    for (int mt = 0; mt < MT; mt++)
#pragma unroll
        for (int nt = 0; nt < NT; nt++)
#pragma unroll
            for (int i = 0; i < 4; i++) acc[mt][nt][i] = 0.0f;

    float4 ra[4];
    float4 rb[BF4PT];

    // ---- gmem load helpers ----
    auto loadA = [&](int k0) {
#pragma unroll
        for (int j = 0; j < 4; j++) {
            int i = t + j * 256;
            int r = i >> 3;
            int kq = (i & 7) << 2;
            ra[j] = *(const float4*)&A[(size_t)(row0 + r) * lda + k0 + kq];
        }
    };
    auto loadB = [&](int k0) {
#pragma unroll
        for (int j = 0; j < BF4PT; j++) {
            int i = t + j * 256;
            int k = i / BNq;
            int nq = (i % BNq) * 4;
            rb[j] = *(const float4*)&Bm[(size_t)(k0 + k) * ldb + col0 + nq];
        }
    };
    auto storeA = [&]() {
#pragma unroll
        for (int j = 0; j < 4; j++) {
            int i = t + j * 256;
            int r = i >> 3;
            int kq = (i & 7) << 2;
            split_pair(&As_h[r][kq], &As_l[r][kq], ra[j].x, ra[j].y);
            split_pair(&As_h[r][kq + 2], &As_l[r][kq + 2], ra[j].z, ra[j].w);
        }
    };
    auto storeB = [&]() {
#pragma unroll
        for (int j = 0; j < BF4PT; j++) {
            int i = t + j * 256;
            int k = i / BNq;
            int nq = (i % BNq) * 4;
            float v[4] = {rb[j].x, rb[j].y, rb[j].z, rb[j].w};
#pragma unroll
            for (int c = 0; c < 4; c++) {
                __nv_bfloat16 h = __float2bfloat16(v[c]);
                float rr = v[c] - __bfloat162float(h);
                Bs_h[nq + c][k] = h;
                Bs_l[nq + c][k] = __float2bfloat16(rr);
            }
        }
    };

    // prologue: tile 0
    loadA(0); loadB(0);
    storeA(); storeB();
    __syncthreads();

    const int ntile = Kd >> 5;
    for (int kt = 0; kt < ntile; kt++) {
        bool more = (kt + 1 < ntile);
        if (more) { loadA((kt + 1) * BK); loadB((kt + 1) * BK); }

        // compute from smem
#pragma unroll
        for (int ks = 0; ks < 2; ks++) {
            const int kh = ks * 16 + 2 * tig;
            uint32_t bh[NT][2], bl[NT][2];
#pragma unroll
            for (int nt = 0; nt < NT; nt++) {
                const __nv_bfloat16* p = &Bs_h[wn + nt * 8 + g][kh];
                bh[nt][0] = *(const uint32_t*)p;
                bh[nt][1] = *(const uint32_t*)(p + 8);
                const __nv_bfloat16* q = &Bs_l[wn + nt * 8 + g][kh];
                bl[nt][0] = *(const uint32_t*)q;
                bl[nt][1] = *(const uint32_t*)(q + 8);
            }
#pragma unroll
            for (int mt = 0; mt < MT; mt++) {
                const __nv_bfloat16* pa = &As_h[wm + mt * 16 + g][kh];
                uint32_t ah0 = *(const uint32_t*)pa;
                uint32_t ah1 = *(const uint32_t*)(pa + 8 * LDK);
                uint32_t ah2 = *(const uint32_t*)(pa + 8);
                uint32_t ah3 = *(const uint32_t*)(pa + 8 * LDK + 8);
                const __nv_bfloat16* qa = &As_l[wm + mt * 16 + g][kh];
                uint32_t al0 = *(const uint32_t*)qa;
                uint32_t al1 = *(const uint32_t*)(qa + 8 * LDK);
                uint32_t al2 = *(const uint32_t*)(qa + 8);
                uint32_t al3 = *(const uint32_t*)(qa + 8 * LDK + 8);
#pragma unroll
                for (int nt = 0; nt < NT; nt++) {
                    mma16816(acc[mt][nt], ah0, ah1, ah2, ah3, bh[nt][0], bh[nt][1]);
                    mma16816(acc[mt][nt], ah0, ah1, ah2, ah3, bl[nt][0], bl[nt][1]);
                    mma16816(acc[mt][nt], al0, al1, al2, al3, bh[nt][0], bh[nt][1]);
                }
            }
        }
        __syncthreads();
        if (more) {
            storeA(); storeB();
            __syncthreads();
        }
    }

    // ---- epilogue ----
#pragma unroll
    for (int mt = 0; mt < MT; mt++) {
#pragma unroll
        for (int nt = 0; nt < NT; nt++) {
            int c = col0 + wn + nt * 8 + 2 * tig;
#pragma unroll
            for (int half = 0; half < 2; half++) {
                int r = row0 + wm + mt * 16 + g + half * 8;
                float v0 = alpha * acc[mt][nt][half * 2 + 0];
                float v1 = alpha * acc[mt][nt][half * 2 + 1];
                if constexpr (EPI == 1) {
                    float2 bb = *(const float2*)&bias[c];
                    v0 += bb.x; v1 += bb.y;
                    v0 = v0 * normcdff(v0);
                    v1 = v1 * normcdff(v1);
                } else if constexpr (EPI == 2) {
                    float2 bb = *(const float2*)&bias[c];
                    float2 rr = *(const float2*)&R[(size_t)r * ldr + c];
                    v0 += bb.x + rr.x; v1 += bb.y + rr.y;
                } else if constexpr (EPI == 3) {
                    float2 rr = *(const float2*)&R[(size_t)r * ldr + c];
                    v0 += rr.x; v1 += rr.y;
                }
                float2 o; o.x = v0; o.y = v1;
                *(float2*)&C[(size_t)r * ldc + c] = o;
            }
        }
    }
}

// ---------------- fused single-query attention (per-b CTA) ----------------
__global__ void __launch_bounds__(256) attn_kernel(const float* __restrict__ xnei,
                                                   const float* __restrict__ Qt,
                                                   float* __restrict__ y) {
    const int b = blockIdx.x;
    __shared__ float xs[KK][260];        // padded: conflict-free LDS.128 both ways
    __shared__ float qs[HH][260];
    __shared__ float spart[2][HH][KK];
    __shared__ float attn_s[HH][KK];
    const int t = threadIdx.x;

    const float4* gx = (const float4*)(xnei + (size_t)b * (KK * DD));
#pragma unroll
    for (int i = 0; i < 8; i++) {
        int idx = i * 256 + t;
        int k = idx >> 6;
        int c4 = idx & 63;
        *(float4*)&xs[k][c4 * 4] = gx[idx];
    }
    const float4* gq = (const float4*)(Qt + (size_t)b * (HH * DD));
#pragma unroll
    for (int i = 0; i < 2; i++) {
        int idx = i * 256 + t;
        int hh = idx >> 6;
        int c4 = idx & 63;
        *(float4*)&qs[hh][c4 * 4] = gq[idx];
    }
    __syncthreads();

    {
        int w = t >> 5, l = t & 31;
        int half = w >> 2;
        int h0 = (w & 3) * 2;
        int k = l;
        int dbase = half * 128;
        float s0 = 0.0f, s1 = 0.0f;
#pragma unroll
        for (int d4 = 0; d4 < 32; d4++) {
            float4 xv = *(const float4*)&xs[k][dbase + d4 * 4];
            float4 q0 = *(const float4*)&qs[h0][dbase + d4 * 4];
            float4 q1 = *(const float4*)&qs[h0 + 1][dbase + d4 * 4];
            s0 = fmaf(xv.x, q0.x, fmaf(xv.y, q0.y, fmaf(xv.z, q0.z, fmaf(xv.w, q0.w, s0))));
            s1 = fmaf(xv.x, q1.x, fmaf(xv.y, q1.y, fmaf(xv.z, q1.z, fmaf(xv.w, q1.w, s1))));
        }
        spart[half][h0][k] = s0;
        spart[half][h0 + 1][k] = s1;
    }
    __syncthreads();

    {
        int w = t >> 5, l = t & 31;
        float s = spart[0][w][l] + spart[1][w][l];
        float m = s;
#pragma unroll
        for (int o = 16; o > 0; o >>= 1) m = fmaxf(m, __shfl_xor_sync(0xffffffffu, m, o));
        float e = expf(s - m);
        float sum = e;
#pragma unroll
        for (int o = 16; o > 0; o >>= 1) sum += __shfl_xor_sync(0xffffffffu, sum, o);
        attn_s[w][l] = e / sum;
    }
    __syncthreads();

    {
        int hp = t >> 6;
        int dg = t & 63;
        int h0 = hp * 2;
        float4 a0 = make_float4(0.f, 0.f, 0.f, 0.f);
        float4 a1 = make_float4(0.f, 0.f, 0.f, 0.f);
#pragma unroll
        for (int k = 0; k < KK; k++) {
            float w0 = attn_s[h0][k];
            float w1 = attn_s[h0 + 1][k];
            float4 xv = *(const float4*)&xs[k][dg * 4];
            a0.x = fmaf(w0, xv.x, a0.x); a0.y = fmaf(w0, xv.y, a0.y);
            a0.z = fmaf(w0, xv.z, a0.z); a0.w = fmaf(w0, xv.w, a0.w);
            a1.x = fmaf(w1, xv.x, a1.x); a1.y = fmaf(w1, xv.y, a1.y);
            a1.z = fmaf(w1, xv.z, a1.z); a1.w = fmaf(w1, xv.w, a1.w);
        }
        float4* gy = (float4*)(y + (size_t)b * (HH * DD));
        gy[h0 * 64 + dg] = a0;
        gy[(h0 + 1) * 64 + dg] = a1;
    }
}

// ---------------- launch ----------------
extern "C" void kernel_launch(void* const* d_in, const int* in_sizes, int n_in,
                              void* d_out, int out_size) {
    (void)in_sizes; (void)n_in; (void)out_size;
    const float* x_anc = (const float*)d_in[0];
    const float* x_nei = (const float*)d_in[1];
    const float* W_q   = (const float*)d_in[2];
    const float* W_k   = (const float*)d_in[3];
    const float* W_v   = (const float*)d_in[4];
    const float* W_o   = (const float*)d_in[5];
    const float* ln1_g = (const float*)d_in[6];
    const float* ln1_b = (const float*)d_in[7];
    const float* ln2_g = (const float*)d_in[8];
    const float* ln2_b = (const float*)d_in[9];
    const float* ff1_w = (const float*)d_in[10];
    const float* ff1_b = (const float*)d_in[11];
    const float* ff2_w = (const float*)d_in[12];
    const float* ff2_b = (const float*)d_in[13];
    float* out = (float*)d_out;

    float *p_xln, *p_Q, *p_Qt, *p_y, *p_v, *p_x, *p_hln, *p_act, *p_WkT;
    cudaGetSymbolAddress((void**)&p_xln, g_xln);
    cudaGetSymbolAddress((void**)&p_Q, g_Q);
    cudaGetSymbolAddress((void**)&p_Qt, g_Qt);
    cudaGetSymbolAddress((void**)&p_y, g_y);
    cudaGetSymbolAddress((void**)&p_v, g_v);
    cudaGetSymbolAddress((void**)&p_x, g_x);
    cudaGetSymbolAddress((void**)&p_hln, g_hln);
    cudaGetSymbolAddress((void**)&p_act, g_act);
    cudaGetSymbolAddress((void**)&p_WkT, g_WkT);

    const float inv_sqrt_dk = 0.17677669529663687f;  // 1/sqrt(32)

    // 0) transpose W_k per head
    prep_wkt<<<DD * DD / 256, 256>>>(W_k, p_WkT);
    // 1) LN1
    ln_kernel<<<BB / 8, 256>>>(x_anc, ln1_g, ln1_b, p_xln);
    // 2) Q = xln @ W_q                         [B,256]x[256,256]
    mma_gemm<64, 32, 32, 0><<<dim3(4, 256, 1), 256>>>(
        p_xln, 256, 0, W_q, 256, 0, p_Q, 256, 0, 256, 1.0f, nullptr, nullptr, 0);
    // 3) Qt_h = (Q_h @ Wk_h^T) / sqrt(dk)      per head: [B,32]x[32,256]
    mma_gemm<64, 32, 32, 0><<<dim3(4, 256, 8), 256>>>(
        p_Q, 256, 32, p_WkT, 256, 32 * 256, p_Qt, 2048, 256, 32, inv_sqrt_dk,
        nullptr, nullptr, 0);
    // 4) attention: scores/softmax/weighted-sum -> y [B,H,D]
    attn_kernel<<<BB, 256>>>(x_nei, p_Qt, p_y);
    // 5) v_h = y_h @ Wv_h                      per head: [B,256]x[256,32]
    mma_gemm<32, 32, 16, 0><<<dim3(1, 256, 8), 256>>>(
        p_y, 2048, 256, W_v, 256, 32, p_v, 256, 32, 256, 1.0f, nullptr, nullptr, 0);
    // 6) x = x_anc + v @ W_o
    mma_gemm<64, 32, 32, 3><<<dim3(4, 256, 1), 256>>>(
        p_v, 256, 0, W_o, 256, 0, p_x, 256, 0, 256, 1.0f, nullptr, x_anc, 256);
    // 7) LN2
    ln_kernel<<<BB / 8, 256>>>(p_x, ln2_g, ln2_b, p_hln);
    // 8) act = gelu(hln @ ff1_w + ff1_b)       [B,256]x[256,1024]
    mma_gemm<64, 32, 32, 1><<<dim3(16, 256, 1), 256>>>(
        p_hln, 256, 0, ff1_w, 1024, 0, p_act, 1024, 0, 256, 1.0f, ff1_b, nullptr, 0);
    // 9) out = x + act @ ff2_w + ff2_b         [B,1024]x[1024,256]
    mma_gemm<64, 32, 32, 2><<<dim3(4, 256, 1), 256>>>(
        p_act, 1024, 0, ff2_w, 256, 0, out, 256, 0, 1024, 1.0f, ff2_b, p_x, 256);
}

// round 7
// speedup vs baseline: 1.9886x; 1.9886x over previous
#include <cuda_runtime.h>
#include <cuda_bf16.h>
#include <math.h>
#include <stdint.h>

#define BB 32768
#define KK 32
#define DD 256
#define HH 8
#define FFD 1024

// ---------------- scratch (static device allocations; no cudaMalloc) ----------------
__device__ float g_xln[BB * DD];
__device__ float g_Q[BB * DD];
__device__ float g_Qt[(size_t)BB * HH * DD];
__device__ float g_y[(size_t)BB * HH * DD];
__device__ float g_v[BB * DD];
__device__ float g_x[BB * DD];
__device__ float g_hln[BB * DD];
__device__ float g_act[(size_t)BB * FFD];

// pre-split bf16 weight planes ([0]=hi, [1]=lo), stored [n][k] K-major
__device__ __align__(256) __nv_bfloat16 s_WqT[2][DD * DD];
__device__ __align__(256) __nv_bfloat16 s_Wk [2][DD * DD];   // no transpose needed
__device__ __align__(256) __nv_bfloat16 s_WvT[2][DD * DD];
__device__ __align__(256) __nv_bfloat16 s_WoT[2][DD * DD];
__device__ __align__(256) __nv_bfloat16 s_f1T[2][DD * FFD];
__device__ __align__(256) __nv_bfloat16 s_f2T[2][DD * FFD];

// ---------------- weight prep: split fp32 -> bf16 hi/lo, optionally transposed ----------------
// W is [Kd][N] row-major; output T[n][k]. Output-indexed: coalesced writes.
__global__ void splitT(const float* __restrict__ W, __nv_bfloat16* __restrict__ Th,
                       __nv_bfloat16* __restrict__ Tl, int Kd, int N) {
    int o = blockIdx.x * 256 + threadIdx.x;      // o = n*Kd + k
    int n = o / Kd, k = o % Kd;
    float v = W[(size_t)k * N + n];
    __nv_bfloat16 h = __float2bfloat16(v);
    Th[o] = h;
    Tl[o] = __float2bfloat16(v - __bfloat162float(h));
}
__global__ void splitN(const float* __restrict__ W, __nv_bfloat16* __restrict__ Sh,
                       __nv_bfloat16* __restrict__ Sl) {
    int o = blockIdx.x * 256 + threadIdx.x;
    float v = W[o];
    __nv_bfloat16 h = __float2bfloat16(v);
    Sh[o] = h;
    Sl[o] = __float2bfloat16(v - __bfloat162float(h));
}

// ---------------- row layernorm: 1 warp per row ----------------
__global__ void __launch_bounds__(256) ln_kernel(const float* __restrict__ X,
                                                 const float* __restrict__ gam,
                                                 const float* __restrict__ bet,
                                                 float* __restrict__ Y) {
    int row = blockIdx.x * 8 + (threadIdx.x >> 5);
    int l = threadIdx.x & 31;
    const float4* xr = (const float4*)(X + (size_t)row * DD);
    float4 v0 = xr[l];
    float4 v1 = xr[l + 32];
    float s = v0.x + v0.y + v0.z + v0.w + v1.x + v1.y + v1.z + v1.w;
    float sq = v0.x * v0.x + v0.y * v0.y + v0.z * v0.z + v0.w * v0.w +
               v1.x * v1.x + v1.y * v1.y + v1.z * v1.z + v1.w * v1.w;
#pragma unroll
    for (int o = 16; o > 0; o >>= 1) {
        s += __shfl_xor_sync(0xffffffffu, s, o);
        sq += __shfl_xor_sync(0xffffffffu, sq, o);
    }
    float mu = s * (1.0f / 256.0f);
    float var = sq * (1.0f / 256.0f) - mu * mu;
    float inv = rsqrtf(var + 1e-5f);
    float4 g0 = ((const float4*)gam)[l];
    float4 g1 = ((const float4*)gam)[l + 32];
    float4 b0 = ((const float4*)bet)[l];
    float4 b1 = ((const float4*)bet)[l + 32];
    float4 o0, o1;
    o0.x = (v0.x - mu) * inv * g0.x + b0.x;
    o0.y = (v0.y - mu) * inv * g0.y + b0.y;
    o0.z = (v0.z - mu) * inv * g0.z + b0.z;
    o0.w = (v0.w - mu) * inv * g0.w + b0.w;
    o1.x = (v1.x - mu) * inv * g1.x + b1.x;
    o1.y = (v1.y - mu) * inv * g1.y + b1.y;
    o1.z = (v1.z - mu) * inv * g1.z + b1.z;
    o1.w = (v1.w - mu) * inv * g1.w + b1.w;
    float4* yr = (float4*)(Y + (size_t)row * DD);
    yr[l] = o0;
    yr[l + 32] = o1;
}

// ---------------- mma / ldmatrix / cp.async primitives ----------------
__device__ __forceinline__ void mma16816(float* c,
                                         uint32_t a0, uint32_t a1, uint32_t a2, uint32_t a3,
                                         uint32_t b0, uint32_t b1) {
    asm volatile(
        "mma.sync.aligned.m16n8k16.row.col.f32.bf16.bf16.f32 "
        "{%0,%1,%2,%3},{%4,%5,%6,%7},{%8,%9},{%0,%1,%2,%3};"
        : "+f"(c[0]), "+f"(c[1]), "+f"(c[2]), "+f"(c[3])
        : "r"(a0), "r"(a1), "r"(a2), "r"(a3), "r"(b0), "r"(b1));
}
__device__ __forceinline__ void ldsm4(uint32_t& r0, uint32_t& r1, uint32_t& r2, uint32_t& r3,
                                      uint32_t addr) {
    asm volatile("ldmatrix.sync.aligned.m8n8.x4.shared.b16 {%0,%1,%2,%3},[%4];"
                 : "=r"(r0), "=r"(r1), "=r"(r2), "=r"(r3) : "r"(addr));
}
__device__ __forceinline__ void cp16(uint32_t saddr, const void* gptr) {
    asm volatile("cp.async.cg.shared.global [%0], [%1], 16;" :: "r"(saddr), "l"(gptr));
}
__device__ __forceinline__ uint32_t sptr(const void* p) {
    return (uint32_t)__cvta_generic_to_shared(p);
}
__device__ __forceinline__ void split_pair(__nv_bfloat16* hp, __nv_bfloat16* lp,
                                           float a, float b) {
    __nv_bfloat16 h0 = __float2bfloat16(a);
    __nv_bfloat16 h1 = __float2bfloat16(b);
    float r0 = a - __bfloat162float(h0);
    float r1 = b - __bfloat162float(h1);
    __nv_bfloat162 hh; hh.x = h0; hh.y = h1;
    __nv_bfloat162 ll; ll.x = __float2bfloat16(r0); ll.y = __float2bfloat16(r1);
    *(__nv_bfloat162*)hp = hh;
    *(__nv_bfloat162*)lp = ll;
}

// ---------------- bf16x3 tensor-core GEMM, ldmatrix + cp.async B ----------------
// A: MxK fp32 row-major (split to smem hi/lo in-kernel).
// B: bf16 hi/lo planes, [n][k] K-major in gmem (pre-split weights) — cp.async, double-buffered.
// EPI 0: alpha*acc | 1: gelu(acc+bias) | 2: acc+bias+R | 3: acc+R
template <int BN, int WM, int WN, int EPI>
__global__ void __launch_bounds__(256) mma_gemm(
    const float* __restrict__ A, int lda, long sA,
    const __nv_bfloat16* __restrict__ Bh_, const __nv_bfloat16* __restrict__ Bl_,
    int ldb, long sB,
    float* __restrict__ C, int ldc, long sC,
    int Kd, float alpha,
    const float* __restrict__ bias,
    const float* __restrict__ R, int ldr) {
    constexpr int BM = 128;
    constexpr int BK = 32;
    constexpr int LDK = 40;                  // 80B row stride: conflict-free for ldmatrix
    constexpr int NWN = BN / WN;
    constexpr int MT = WM / 16;
    constexpr int NT = WN / 8;
    static_assert((BM / WM) * (BN / WN) == 8, "8 warps");

    __shared__ __align__(16) __nv_bfloat16 As_h[BM][LDK];
    __shared__ __align__(16) __nv_bfloat16 As_l[BM][LDK];
    __shared__ __align__(16) __nv_bfloat16 Bs_h[2][BN][LDK];
    __shared__ __align__(16) __nv_bfloat16 Bs_l[2][BN][LDK];

    A += (size_t)blockIdx.z * sA;
    const __nv_bfloat16* Bh = Bh_ + (size_t)blockIdx.z * sB;
    const __nv_bfloat16* Bl = Bl_ + (size_t)blockIdx.z * sB;
    C += (size_t)blockIdx.z * sC;

    const int t = threadIdx.x;
    const int w = t >> 5;
    const int lane = t & 31;
    const int g = lane >> 2;
    const int tig = lane & 3;
    const int wm = (w / NWN) * WM;
    const int wn = (w % NWN) * WN;
    const int row0 = blockIdx.y * BM;
    const int col0 = blockIdx.x * BN;

    float acc[MT][NT][4];
#pragma unroll
    for (int mt = 0; mt < MT; mt++)
#pragma unroll
        for (int nt = 0; nt < NT; nt++)
#pragma unroll
            for (int i = 0; i < 4; i++) acc[mt][nt][i] = 0.0f;

    float4 ra[4];

    auto loadA = [&](int k0) {
#pragma unroll
        for (int j = 0; j < 4; j++) {
            int i = t + j * 256;
            int r = i >> 3;
            int kq = (i & 7) << 2;
            ra[j] = *(const float4*)&A[(size_t)(row0 + r) * lda + k0 + kq];
        }
    };
    auto storeA = [&]() {
#pragma unroll
        for (int j = 0; j < 4; j++) {
            int i = t + j * 256;
            int r = i >> 3;
            int kq = (i & 7) << 2;
            split_pair(&As_h[r][kq], &As_l[r][kq], ra[j].x, ra[j].y);
            split_pair(&As_h[r][kq + 2], &As_l[r][kq + 2], ra[j].z, ra[j].w);
        }
    };
    auto stageB = [&](int k0, int buf) {
        constexpr int TOT = BN * 4;          // 16B chunks per plane
        if (TOT == 256 || t < TOT) {
            int n = t >> 2, ch = t & 3;
            size_t go = (size_t)(col0 + n) * ldb + k0 + ch * 8;
            cp16(sptr(&Bs_h[buf][n][ch * 8]), Bh + go);
            cp16(sptr(&Bs_l[buf][n][ch * 8]), Bl + go);
        }
        asm volatile("cp.async.commit_group;");
    };

    // prologue: tile 0
    loadA(0);
    storeA();
    stageB(0, 0);
    asm volatile("cp.async.wait_group 0;" ::: "memory");
    __syncthreads();

    // ldmatrix lane-address components
    const int a_row = lane & 15;             // + (lane>>4)*8 column offset
    const int a_c8 = (lane >> 4) << 3;
    const int b_row = ((lane >> 4) << 3) + (lane & 7);
    const int b_c8 = ((lane >> 3) & 1) << 3;

    const int ntile = Kd >> 5;
    for (int kt = 0; kt < ntile; kt++) {
        const int cur = kt & 1;
        const bool more = (kt + 1 < ntile);
        if (more) { stageB((kt + 1) * BK, cur ^ 1); loadA((kt + 1) * BK); }

#pragma unroll
        for (int ks = 0; ks < 2; ks++) {
            const int kh = ks * 16;
            uint32_t bh[NT][2], bl[NT][2];
#pragma unroll
            for (int ntp = 0; ntp < NT / 2; ntp++) {
                uint32_t ba = sptr(&Bs_h[cur][wn + ntp * 16 + b_row][kh + b_c8]);
                ldsm4(bh[2 * ntp][0], bh[2 * ntp][1], bh[2 * ntp + 1][0], bh[2 * ntp + 1][1], ba);
                uint32_t bb = sptr(&Bs_l[cur][wn + ntp * 16 + b_row][kh + b_c8]);
                ldsm4(bl[2 * ntp][0], bl[2 * ntp][1], bl[2 * ntp + 1][0], bl[2 * ntp + 1][1], bb);
            }
#pragma unroll
            for (int mt = 0; mt < MT; mt++) {
                uint32_t ah0, ah1, ah2, ah3, al0, al1, al2, al3;
                ldsm4(ah0, ah1, ah2, ah3, sptr(&As_h[wm + mt * 16 + a_row][kh + a_c8]));
                ldsm4(al0, al1, al2, al3, sptr(&As_l[wm + mt * 16 + a_row][kh + a_c8]));
#pragma unroll
                for (int nt = 0; nt < NT; nt++) {
                    mma16816(acc[mt][nt], ah0, ah1, ah2, ah3, bh[nt][0], bh[nt][1]);
                    mma16816(acc[mt][nt], ah0, ah1, ah2, ah3, bl[nt][0], bl[nt][1]);
                    mma16816(acc[mt][nt], al0, al1, al2, al3, bh[nt][0], bh[nt][1]);
                }
            }
        }
        __syncthreads();
        if (more) {
            storeA();
            asm volatile("cp.async.wait_group 0;" ::: "memory");
            __syncthreads();
        }
    }

    // ---- epilogue ----
#pragma unroll
    for (int mt = 0; mt < MT; mt++) {
#pragma unroll
        for (int nt = 0; nt < NT; nt++) {
            int c = col0 + wn + nt * 8 + 2 * tig;
#pragma unroll
            for (int half = 0; half < 2; half++) {
                int r = row0 + wm + mt * 16 + g + half * 8;
                float v0 = alpha * acc[mt][nt][half * 2 + 0];
                float v1 = alpha * acc[mt][nt][half * 2 + 1];
                if constexpr (EPI == 1) {
                    float2 bb = *(const float2*)&bias[c];
                    v0 += bb.x; v1 += bb.y;
                    v0 = v0 * normcdff(v0);
                    v1 = v1 * normcdff(v1);
                } else if constexpr (EPI == 2) {
                    float2 bb = *(const float2*)&bias[c];
                    float2 rr = *(const float2*)&R[(size_t)r * ldr + c];
                    v0 += bb.x + rr.x; v1 += bb.y + rr.y;
                } else if constexpr (EPI == 3) {
                    float2 rr = *(const float2*)&R[(size_t)r * ldr + c];
                    v0 += rr.x; v1 += rr.y;
                }
                float2 o; o.x = v0; o.y = v1;
                *(float2*)&C[(size_t)r * ldc + c] = o;
            }
        }
    }
}

// ---------------- fused single-query attention (per-b CTA) ----------------
__global__ void __launch_bounds__(256) attn_kernel(const float* __restrict__ xnei,
                                                   const float* __restrict__ Qt,
                                                   float* __restrict__ y) {
    const int b = blockIdx.x;
    __shared__ float xs[KK][260];
    __shared__ float qs[HH][260];
    __shared__ float spart[2][HH][KK];
    __shared__ float attn_s[HH][KK];
    const int t = threadIdx.x;

    const float4* gx = (const float4*)(xnei + (size_t)b * (KK * DD));
#pragma unroll
    for (int i = 0; i < 8; i++) {
        int idx = i * 256 + t;
        int k = idx >> 6;
        int c4 = idx & 63;
        *(float4*)&xs[k][c4 * 4] = gx[idx];
    }
    const float4* gq = (const float4*)(Qt + (size_t)b * (HH * DD));
#pragma unroll
    for (int i = 0; i < 2; i++) {
        int idx = i * 256 + t;
        int hh = idx >> 6;
        int c4 = idx & 63;
        *(float4*)&qs[hh][c4 * 4] = gq[idx];
    }
    __syncthreads();

    {
        int w = t >> 5, l = t & 31;
        int half = w >> 2;
        int h0 = (w & 3) * 2;
        int k = l;
        int dbase = half * 128;
        float s0 = 0.0f, s1 = 0.0f;
#pragma unroll
        for (int d4 = 0; d4 < 32; d4++) {
            float4 xv = *(const float4*)&xs[k][dbase + d4 * 4];
            float4 q0 = *(const float4*)&qs[h0][dbase + d4 * 4];
            float4 q1 = *(const float4*)&qs[h0 + 1][dbase + d4 * 4];
            s0 = fmaf(xv.x, q0.x, fmaf(xv.y, q0.y, fmaf(xv.z, q0.z, fmaf(xv.w, q0.w, s0))));
            s1 = fmaf(xv.x, q1.x, fmaf(xv.y, q1.y, fmaf(xv.z, q1.z, fmaf(xv.w, q1.w, s1))));
        }
        spart[half][h0][k] = s0;
        spart[half][h0 + 1][k] = s1;
    }
    __syncthreads();

    {
        int w = t >> 5, l = t & 31;
        float s = spart[0][w][l] + spart[1][w][l];
        float m = s;
#pragma unroll
        for (int o = 16; o > 0; o >>= 1) m = fmaxf(m, __shfl_xor_sync(0xffffffffu, m, o));
        float e = expf(s - m);
        float sum = e;
#pragma unroll
        for (int o = 16; o > 0; o >>= 1) sum += __shfl_xor_sync(0xffffffffu, sum, o);
        attn_s[w][l] = e / sum;
    }
    __syncthreads();

    {
        int hp = t >> 6;
        int dg = t & 63;
        int h0 = hp * 2;
        float4 a0 = make_float4(0.f, 0.f, 0.f, 0.f);
        float4 a1 = make_float4(0.f, 0.f, 0.f, 0.f);
#pragma unroll
        for (int k = 0; k < KK; k++) {
            float w0 = attn_s[h0][k];
            float w1 = attn_s[h0 + 1][k];
            float4 xv = *(const float4*)&xs[k][dg * 4];
            a0.x = fmaf(w0, xv.x, a0.x); a0.y = fmaf(w0, xv.y, a0.y);
            a0.z = fmaf(w0, xv.z, a0.z); a0.w = fmaf(w0, xv.w, a0.w);
            a1.x = fmaf(w1, xv.x, a1.x); a1.y = fmaf(w1, xv.y, a1.y);
            a1.z = fmaf(w1, xv.z, a1.z); a1.w = fmaf(w1, xv.w, a1.w);
        }
        float4* gy = (float4*)(y + (size_t)b * (HH * DD));
        gy[h0 * 64 + dg] = a0;
        gy[(h0 + 1) * 64 + dg] = a1;
    }
}

// ---------------- launch ----------------
extern "C" void kernel_launch(void* const* d_in, const int* in_sizes, int n_in,
                              void* d_out, int out_size) {
    (void)in_sizes; (void)n_in; (void)out_size;
    const float* x_anc = (const float*)d_in[0];
    const float* x_nei = (const float*)d_in[1];
    const float* W_q   = (const float*)d_in[2];
    const float* W_k   = (const float*)d_in[3];
    const float* W_v   = (const float*)d_in[4];
    const float* W_o   = (const float*)d_in[5];
    const float* ln1_g = (const float*)d_in[6];
    const float* ln1_b = (const float*)d_in[7];
    const float* ln2_g = (const float*)d_in[8];
    const float* ln2_b = (const float*)d_in[9];
    const float* ff1_w = (const float*)d_in[10];
    const float* ff1_b = (const float*)d_in[11];
    const float* ff2_w = (const float*)d_in[12];
    const float* ff2_b = (const float*)d_in[13];
    float* out = (float*)d_out;

    float *p_xln, *p_Q, *p_Qt, *p_y, *p_v, *p_x, *p_hln, *p_act;
    cudaGetSymbolAddress((void**)&p_xln, g_xln);
    cudaGetSymbolAddress((void**)&p_Q, g_Q);
    cudaGetSymbolAddress((void**)&p_Qt, g_Qt);
    cudaGetSymbolAddress((void**)&p_y, g_y);
    cudaGetSymbolAddress((void**)&p_v, g_v);
    cudaGetSymbolAddress((void**)&p_x, g_x);
    cudaGetSymbolAddress((void**)&p_hln, g_hln);
    cudaGetSymbolAddress((void**)&p_act, g_act);

    __nv_bfloat16 *p_WqT, *p_Wk, *p_WvT, *p_WoT, *p_f1T, *p_f2T;
    cudaGetSymbolAddress((void**)&p_WqT, s_WqT);
    cudaGetSymbolAddress((void**)&p_Wk, s_Wk);
    cudaGetSymbolAddress((void**)&p_WvT, s_WvT);
    cudaGetSymbolAddress((void**)&p_WoT, s_WoT);
    cudaGetSymbolAddress((void**)&p_f1T, s_f1T);
    cudaGetSymbolAddress((void**)&p_f2T, s_f2T);
    const int WD = DD * DD;        // plane stride, small weights
    const int WF = DD * FFD;       // plane stride, ff weights

    const float inv_sqrt_dk = 0.17677669529663687f;  // 1/sqrt(32)

    // 0) weight prep: split (+transpose) to bf16 hi/lo planes
    splitT<<<256, 256>>>(W_q, p_WqT, p_WqT + WD, 256, 256);
    splitN<<<256, 256>>>(W_k, p_Wk, p_Wk + WD);
    splitT<<<256, 256>>>(W_v, p_WvT, p_WvT + WD, 256, 256);
    splitT<<<256, 256>>>(W_o, p_WoT, p_WoT + WD, 256, 256);
    splitT<<<1024, 256>>>(ff1_w, p_f1T, p_f1T + WF, 256, 1024);
    splitT<<<1024, 256>>>(ff2_w, p_f2T, p_f2T + WF, 1024, 256);

    // 1) LN1
    ln_kernel<<<BB / 8, 256>>>(x_anc, ln1_g, ln1_b, p_xln);
    // 2) Q = xln @ W_q
    mma_gemm<64, 32, 32, 0><<<dim3(4, 256, 1), 256>>>(
        p_xln, 256, 0, p_WqT, p_WqT + WD, 256, 0, p_Q, 256, 0, 256, 1.0f, nullptr, nullptr, 0);
    // 3) Qt_h = (Q_h @ Wk_h^T)/sqrt(dk); B = W_k rows directly (Bt[d][j] = W_k[d][h*32+j])
    mma_gemm<64, 32, 32, 0><<<dim3(4, 256, 8), 256>>>(
        p_Q, 256, 32, p_Wk, p_Wk + WD, 256, 32, p_Qt, 2048, 256, 32, inv_sqrt_dk,
        nullptr, nullptr, 0);
    // 4) attention
    attn_kernel<<<BB, 256>>>(x_nei, p_Qt, p_y);
    // 5) v_h = y_h @ Wv_h   (Bt rows = WvT[h*32 + j][d])
    mma_gemm<32, 32, 16, 0><<<dim3(1, 256, 8), 256>>>(
        p_y, 2048, 256, p_WvT, p_WvT + WD, 256, 32 * 256, p_v, 256, 32, 256, 1.0f,
        nullptr, nullptr, 0);
    // 6) x = x_anc + v @ W_o
    mma_gemm<64, 32, 32, 3><<<dim3(4, 256, 1), 256>>>(
        p_v, 256, 0, p_WoT, p_WoT + WD, 256, 0, p_x, 256, 0, 256, 1.0f, nullptr, x_anc, 256);
    // 7) LN2
    ln_kernel<<<BB / 8, 256>>>(p_x, ln2_g, ln2_b, p_hln);
    // 8) act = gelu(hln @ ff1_w + ff1_b)
    mma_gemm<64, 32, 32, 1><<<dim3(16, 256, 1), 256>>>(
        p_hln, 256, 0, p_f1T, p_f1T + WF, 256, 0, p_act, 1024, 0, 256, 1.0f, ff1_b,
        nullptr, 0);
    // 9) out = x + act @ ff2_w + ff2_b
    mma_gemm<64, 32, 32, 2><<<dim3(4, 256, 1), 256>>>(
        p_act, 1024, 0, p_f2T, p_f2T + WF, 1024, 0, out, 256, 0, 1024, 1.0f, ff2_b,
        p_x, 256);
}

// round 9
// speedup vs baseline: 2.0039x; 1.0077x over previous
#include <cuda_runtime.h>
#include <cuda_bf16.h>
#include <math.h>
#include <stdint.h>

#define BB 32768
#define KK 32
#define DD 256
#define HH 8
#define FFD 1024

#define AP ((size_t)BB * DD)          // activation plane  [B,256]
#define YP ((size_t)BB * HH * DD)     // y plane           [B,2048]
#define FP ((size_t)BB * FFD)         // ff plane          [B,1024]

// ---------------- scratch (static device; no cudaMalloc) ----------------
// split bf16 activation planes: [0]=hi, [1]=lo contiguous
__device__ __align__(256) __nv_bfloat16 a_xln[2 * AP];
__device__ __align__(256) __nv_bfloat16 a_Q[2 * AP];
__device__ __align__(256) __nv_bfloat16 a_y[2 * YP];
__device__ __align__(256) __nv_bfloat16 a_v[2 * AP];
__device__ __align__(256) __nv_bfloat16 a_hln[2 * AP];
__device__ __align__(256) __nv_bfloat16 a_act[2 * FP];
// fp32 scratch
__device__ float g_Qt[YP];
__device__ float g_x[AP];

// pre-split bf16 weight planes ([0]=hi,[1]=lo), stored [n][k] K-major
__device__ __align__(256) __nv_bfloat16 s_WqT[2][DD * DD];
__device__ __align__(256) __nv_bfloat16 s_Wk [2][DD * DD];   // used untransposed
__device__ __align__(256) __nv_bfloat16 s_WvT[2][DD * DD];
__device__ __align__(256) __nv_bfloat16 s_WoT[2][DD * DD];
__device__ __align__(256) __nv_bfloat16 s_f1T[2][DD * FFD];
__device__ __align__(256) __nv_bfloat16 s_f2T[2][DD * FFD];

// ---------------- small helpers ----------------
__device__ __forceinline__ void splitf(float v, __nv_bfloat16& h, __nv_bfloat16& l) {
    h = __float2bfloat16(v);
    l = __float2bfloat16(v - __bfloat162float(h));
}
__device__ __forceinline__ void split2v(float a, float b,
                                        __nv_bfloat162& h, __nv_bfloat162& l) {
    __nv_bfloat16 ha, la, hb, lb;
    splitf(a, ha, la);
    splitf(b, hb, lb);
    h.x = ha; h.y = hb;
    l.x = la; l.y = lb;
}
__device__ __forceinline__ uint32_t sptrs(const void* p) {
    return (uint32_t)__cvta_generic_to_shared(p);
}
__device__ __forceinline__ void cp16(uint32_t saddr, const void* gptr) {
    asm volatile("cp.async.cg.shared.global [%0], [%1], 16;" :: "r"(saddr), "l"(gptr));
}
__device__ __forceinline__ void mma16816(float* c,
                                         uint32_t a0, uint32_t a1, uint32_t a2, uint32_t a3,
                                         uint32_t b0, uint32_t b1) {
    asm volatile(
        "mma.sync.aligned.m16n8k16.row.col.f32.bf16.bf16.f32 "
        "{%0,%1,%2,%3},{%4,%5,%6,%7},{%8,%9},{%0,%1,%2,%3};"
        : "+f"(c[0]), "+f"(c[1]), "+f"(c[2]), "+f"(c[3])
        : "r"(a0), "r"(a1), "r"(a2), "r"(a3), "r"(b0), "r"(b1));
}
__device__ __forceinline__ void ldsm4(uint32_t& r0, uint32_t& r1, uint32_t& r2, uint32_t& r3,
                                      uint32_t addr) {
    asm volatile("ldmatrix.sync.aligned.m8n8.x4.shared.b16 {%0,%1,%2,%3},[%4];"
                 : "=r"(r0), "=r"(r1), "=r"(r2), "=r"(r3) : "r"(addr));
}

// ---------------- weight prep ----------------
// tiled transpose+split: W [Kd][N] row-major -> T[n][k] hi/lo planes. blockDim (32,8).
__global__ void splitT2(const float* __restrict__ W, __nv_bfloat16* __restrict__ Th,
                        __nv_bfloat16* __restrict__ Tl, int Kd, int N) {
    __shared__ float tile[32][33];
    int n0 = blockIdx.x * 32, k0 = blockIdx.y * 32;
    int tx = threadIdx.x, ty = threadIdx.y;
#pragma unroll
    for (int i = 0; i < 4; i++)
        tile[ty + i * 8][tx] = W[(size_t)(k0 + ty + i * 8) * N + n0 + tx];
    __syncthreads();
#pragma unroll
    for (int i = 0; i < 4; i++) {
        int nn = ty + i * 8;
        float v = tile[tx][nn];
        __nv_bfloat16 h, l;
        splitf(v, h, l);
        size_t o = (size_t)(n0 + nn) * Kd + k0 + tx;
        Th[o] = h;
        Tl[o] = l;
    }
}
// no-transpose split (W_k used as-is)
__global__ void splitN(const float* __restrict__ W, __nv_bfloat16* __restrict__ Sh,
                       __nv_bfloat16* __restrict__ Sl) {
    int o = blockIdx.x * 256 + threadIdx.x;
    float v = W[o];
    __nv_bfloat16 h, l;
    splitf(v, h, l);
    Sh[o] = h;
    Sl[o] = l;
}

// ---------------- layernorm -> split bf16 planes (1 warp/row) ----------------
__global__ void __launch_bounds__(256) ln_split(const float* __restrict__ X,
                                                const float* __restrict__ gam,
                                                const float* __restrict__ bet,
                                                __nv_bfloat16* __restrict__ Yh,
                                                __nv_bfloat16* __restrict__ Yl) {
    int row = blockIdx.x * 8 + (threadIdx.x >> 5);
    int l = threadIdx.x & 31;
    const float4* xr = (const float4*)(X + (size_t)row * DD);
    float4 v0 = xr[l];
    float4 v1 = xr[l + 32];
    float s = v0.x + v0.y + v0.z + v0.w + v1.x + v1.y + v1.z + v1.w;
    float sq = v0.x * v0.x + v0.y * v0.y + v0.z * v0.z + v0.w * v0.w +
               v1.x * v1.x + v1.y * v1.y + v1.z * v1.z + v1.w * v1.w;
#pragma unroll
    for (int o = 16; o > 0; o >>= 1) {
        s += __shfl_xor_sync(0xffffffffu, s, o);
        sq += __shfl_xor_sync(0xffffffffu, sq, o);
    }
    float mu = s * (1.0f / 256.0f);
    float var = sq * (1.0f / 256.0f) - mu * mu;
    float inv = rsqrtf(var + 1e-5f);
    float4 g0 = ((const float4*)gam)[l];
    float4 g1 = ((const float4*)gam)[l + 32];
    float4 b0 = ((const float4*)bet)[l];
    float4 b1 = ((const float4*)bet)[l + 32];
    float o0x = (v0.x - mu) * inv * g0.x + b0.x;
    float o0y = (v0.y - mu) * inv * g0.y + b0.y;
    float o0z = (v0.z - mu) * inv * g0.z + b0.z;
    float o0w = (v0.w - mu) * inv * g0.w + b0.w;
    float o1x = (v1.x - mu) * inv * g1.x + b1.x;
    float o1y = (v1.y - mu) * inv * g1.y + b1.y;
    float o1z = (v1.z - mu) * inv * g1.z + b1.z;
    float o1w = (v1.w - mu) * inv * g1.w + b1.w;
    __nv_bfloat162 h0, l0, h1, l1, h2, l2, h3, l3;
    split2v(o0x, o0y, h0, l0);
    split2v(o0z, o0w, h1, l1);
    split2v(o1x, o1y, h2, l2);
    split2v(o1z, o1w, h3, l3);
    size_t base = (size_t)row * DD + 4 * l;
    *(__nv_bfloat162*)&Yh[base] = h0;
    *(__nv_bfloat162*)&Yh[base + 2] = h1;
    *(__nv_bfloat162*)&Yh[base + 128] = h2;
    *(__nv_bfloat162*)&Yh[base + 130] = h3;
    *(__nv_bfloat162*)&Yl[base] = l0;
    *(__nv_bfloat162*)&Yl[base + 2] = l1;
    *(__nv_bfloat162*)&Yl[base + 128] = l2;
    *(__nv_bfloat162*)&Yl[base + 130] = l3;
}

// ---------------- bf16x3 tensor-core GEMM: all-cp.async, fully double-buffered ----------------
// A: bf16 hi/lo planes [r][k] (lda), B: bf16 hi/lo planes [n][k] (ldb).
// EPI 0: alpha*acc | 1: gelu(acc+bias) | 2: acc+bias+R | 3: acc+R
// OUTS 0: fp32 Cf | 1: split bf16 planes Ch/Cl
template <int BN, int WM, int WN, int EPI, int OUTS>
__global__ void __launch_bounds__(256) mma_gemm2(
    const __nv_bfloat16* __restrict__ Ah_, const __nv_bfloat16* __restrict__ Al_,
    int lda, long sA,
    const __nv_bfloat16* __restrict__ Bh_, const __nv_bfloat16* __restrict__ Bl_,
    int ldb, long sB,
    float* __restrict__ Cf, __nv_bfloat16* __restrict__ Ch, __nv_bfloat16* __restrict__ Cl,
    int ldc, long sC,
    int Kd, float alpha,
    const float* __restrict__ bias,
    const float* __restrict__ R, int ldr) {
    constexpr int BM = 128;
    constexpr int BK = 32;
    constexpr int LDK = 40;                  // 80B row stride: ldmatrix conflict-free
    constexpr int NWN = BN / WN;
    constexpr int MT = WM / 16;
    constexpr int NT = WN / 8;
    static_assert((BM / WM) * (BN / WN) == 8, "8 warps");

    __shared__ __align__(16) __nv_bfloat16 As_h[2][BM][LDK];
    __shared__ __align__(16) __nv_bfloat16 As_l[2][BM][LDK];
    __shared__ __align__(16) __nv_bfloat16 Bs_h[2][BN][LDK];
    __shared__ __align__(16) __nv_bfloat16 Bs_l[2][BN][LDK];

    const __nv_bfloat16* Ah = Ah_ + (size_t)blockIdx.z * sA;
    const __nv_bfloat16* Al = Al_ + (size_t)blockIdx.z * sA;
    const __nv_bfloat16* Bh = Bh_ + (size_t)blockIdx.z * sB;
    const __nv_bfloat16* Bl = Bl_ + (size_t)blockIdx.z * sB;
    if (OUTS == 0) Cf += (size_t)blockIdx.z * sC;
    else { Ch += (size_t)blockIdx.z * sC; Cl += (size_t)blockIdx.z * sC; }

    const int t = threadIdx.x;
    const int w = t >> 5;
    const int lane = t & 31;
    const int g = lane >> 2;
    const int tig = lane & 3;
    const int wm = (w / NWN) * WM;
    const int wn = (w % NWN) * WN;
    const int row0 = blockIdx.y * BM;
    const int col0 = blockIdx.x * BN;

    float acc[MT][NT][4];
#pragma unroll
    for (int mt = 0; mt < MT; mt++)
#pragma unroll
        for (int nt = 0; nt < NT; nt++)
#pragma unroll
            for (int i = 0; i < 4; i++) acc[mt][nt][i] = 0.0f;

    auto stage = [&](int k0, int buf) {
#pragma unroll
        for (int idx = t; idx < BM * 4; idx += 256) {       // A: 512 16B chunks/plane
            int r = idx >> 2, ch = idx & 3;
            size_t go = (size_t)(row0 + r) * lda + k0 + ch * 8;
            cp16(sptrs(&As_h[buf][r][ch * 8]), Ah + go);
            cp16(sptrs(&As_l[buf][r][ch * 8]), Al + go);
        }
#pragma unroll
        for (int idx = t; idx < BN * 4; idx += 256) {       // B
            int n = idx >> 2, ch = idx & 3;
            size_t go = (size_t)(col0 + n) * ldb + k0 + ch * 8;
            cp16(sptrs(&Bs_h[buf][n][ch * 8]), Bh + go);
            cp16(sptrs(&Bs_l[buf][n][ch * 8]), Bl + go);
        }
        asm volatile("cp.async.commit_group;");
    };

    stage(0, 0);
    asm volatile("cp.async.wait_group 0;" ::: "memory");
    __syncthreads();

    const int a_row = lane & 15;
    const int a_c8 = (lane >> 4) << 3;
    const int b_row = ((lane >> 4) << 3) + (lane & 7);
    const int b_c8 = ((lane >> 3) & 1) << 3;

    const int ntile = Kd >> 5;
    for (int kt = 0; kt < ntile; kt++) {
        const int cur = kt & 1;
        const bool more = (kt + 1 < ntile);
        if (more) stage((kt + 1) * BK, cur ^ 1);

#pragma unroll
        for (int ks = 0; ks < 2; ks++) {
            const int kh = ks * 16;
            uint32_t bh[NT][2], bl[NT][2];
#pragma unroll
            for (int ntp = 0; ntp < NT / 2; ntp++) {
                uint32_t ba = sptrs(&Bs_h[cur][wn + ntp * 16 + b_row][kh + b_c8]);
                ldsm4(bh[2 * ntp][0], bh[2 * ntp][1], bh[2 * ntp + 1][0], bh[2 * ntp + 1][1], ba);
                uint32_t bb = sptrs(&Bs_l[cur][wn + ntp * 16 + b_row][kh + b_c8]);
                ldsm4(bl[2 * ntp][0], bl[2 * ntp][1], bl[2 * ntp + 1][0], bl[2 * ntp + 1][1], bb);
            }
#pragma unroll
            for (int mt = 0; mt < MT; mt++) {
                uint32_t ah0, ah1, ah2, ah3, al0, al1, al2, al3;
                ldsm4(ah0, ah1, ah2, ah3, sptrs(&As_h[cur][wm + mt * 16 + a_row][kh + a_c8]));
                ldsm4(al0, al1, al2, al3, sptrs(&As_l[cur][wm + mt * 16 + a_row][kh + a_c8]));
#pragma unroll
                for (int nt = 0; nt < NT; nt++) {
                    mma16816(acc[mt][nt], ah0, ah1, ah2, ah3, bh[nt][0], bh[nt][1]);
                    mma16816(acc[mt][nt], ah0, ah1, ah2, ah3, bl[nt][0], bl[nt][1]);
                    mma16816(acc[mt][nt], al0, al1, al2, al3, bh[nt][0], bh[nt][1]);
                }
            }
        }
        if (more) asm volatile("cp.async.wait_group 0;" ::: "memory");
        __syncthreads();
    }

    // ---- epilogue ----
#pragma unroll
    for (int mt = 0; mt < MT; mt++) {
#pragma unroll
        for (int nt = 0; nt < NT; nt++) {
            int c = col0 + wn + nt * 8 + 2 * tig;
#pragma unroll
            for (int half = 0; half < 2; half++) {
                int r = row0 + wm + mt * 16 + g + half * 8;
                float v0 = alpha * acc[mt][nt][half * 2 + 0];
                float v1 = alpha * acc[mt][nt][half * 2 + 1];
                if constexpr (EPI == 1) {
                    float2 bb = *(const float2*)&bias[c];
                    v0 += bb.x; v1 += bb.y;
                    v0 = v0 * normcdff(v0);
                    v1 = v1 * normcdff(v1);
                } else if constexpr (EPI == 2) {
                    float2 bb = *(const float2*)&bias[c];
                    float2 rr = *(const float2*)&R[(size_t)r * ldr + c];
                    v0 += bb.x + rr.x; v1 += bb.y + rr.y;
                } else if constexpr (EPI == 3) {
                    float2 rr = *(const float2*)&R[(size_t)r * ldr + c];
                    v0 += rr.x; v1 += rr.y;
                }
                if constexpr (OUTS == 0) {
                    float2 o; o.x = v0; o.y = v1;
                    *(float2*)&Cf[(size_t)r * ldc + c] = o;
                } else {
                    __nv_bfloat162 hh, ll;
                    split2v(v0, v1, hh, ll);
                    *(__nv_bfloat162*)&Ch[(size_t)r * ldc + c] = hh;
                    *(__nv_bfloat162*)&Cl[(size_t)r * ldc + c] = ll;
                }
            }
        }
    }
}

// ---------------- fused single-query attention (per-b CTA) ----------------
// reads Qt fp32, writes y as split bf16 planes.
__global__ void __launch_bounds__(256) attn_kernel(const float* __restrict__ xnei,
                                                   const float* __restrict__ Qt,
                                                   __nv_bfloat16* __restrict__ yh,
                                                   __nv_bfloat16* __restrict__ yl) {
    const int b = blockIdx.x;
    __shared__ float xs[KK][260];
    __shared__ float qs[HH][260];
    __shared__ float spart[2][HH][KK];
    __shared__ float attn_s[HH][KK];
    const int t = threadIdx.x;

    const float4* gx = (const float4*)(xnei + (size_t)b * (KK * DD));
#pragma unroll
    for (int i = 0; i < 8; i++) {
        int idx = i * 256 + t;
        int k = idx >> 6;
        int c4 = idx & 63;
        *(float4*)&xs[k][c4 * 4] = gx[idx];
    }
    const float4* gq = (const float4*)(Qt + (size_t)b * (HH * DD));
#pragma unroll
    for (int i = 0; i < 2; i++) {
        int idx = i * 256 + t;
        int hh = idx >> 6;
        int c4 = idx & 63;
        *(float4*)&qs[hh][c4 * 4] = gq[idx];
    }
    __syncthreads();

    {
        int w = t >> 5, l = t & 31;
        int half = w >> 2;
        int h0 = (w & 3) * 2;
        int k = l;
        int dbase = half * 128;
        float s0 = 0.0f, s1 = 0.0f;
#pragma unroll
        for (int d4 = 0; d4 < 32; d4++) {
            float4 xv = *(const float4*)&xs[k][dbase + d4 * 4];
            float4 q0 = *(const float4*)&qs[h0][dbase + d4 * 4];
            float4 q1 = *(const float4*)&qs[h0 + 1][dbase + d4 * 4];
            s0 = fmaf(xv.x, q0.x, fmaf(xv.y, q0.y, fmaf(xv.z, q0.z, fmaf(xv.w, q0.w, s0))));
            s1 = fmaf(xv.x, q1.x, fmaf(xv.y, q1.y, fmaf(xv.z, q1.z, fmaf(xv.w, q1.w, s1))));
        }
        spart[half][h0][k] = s0;
        spart[half][h0 + 1][k] = s1;
    }
    __syncthreads();

    {
        int w = t >> 5, l = t & 31;
        float s = spart[0][w][l] + spart[1][w][l];
        float m = s;
#pragma unroll
        for (int o = 16; o > 0; o >>= 1) m = fmaxf(m, __shfl_xor_sync(0xffffffffu, m, o));
        float e = expf(s - m);
        float sum = e;
#pragma unroll
        for (int o = 16; o > 0; o >>= 1) sum += __shfl_xor_sync(0xffffffffu, sum, o);
        attn_s[w][l] = e / sum;
    }
    __syncthreads();

    {
        int hp = t >> 6;
        int dg = t & 63;
        int h0 = hp * 2;
        float4 a0 = make_float4(0.f, 0.f, 0.f, 0.f);
        float4 a1 = make_float4(0.f, 0.f, 0.f, 0.f);
#pragma unroll
        for (int k = 0; k < KK; k++) {
            float w0 = attn_s[h0][k];
            float w1 = attn_s[h0 + 1][k];
            float4 xv = *(const float4*)&xs[k][dg * 4];
            a0.x = fmaf(w0, xv.x, a0.x); a0.y = fmaf(w0, xv.y, a0.y);
            a0.z = fmaf(w0, xv.z, a0.z); a0.w = fmaf(w0, xv.w, a0.w);
            a1.x = fmaf(w1, xv.x, a1.x); a1.y = fmaf(w1, xv.y, a1.y);
            a1.z = fmaf(w1, xv.z, a1.z); a1.w = fmaf(w1, xv.w, a1.w);
        }
        size_t base0 = (size_t)b * (HH * DD) + (size_t)h0 * DD + dg * 4;
        size_t base1 = base0 + DD;
        __nv_bfloat162 h0a, l0a, h0b, l0b, h1a, l1a, h1b, l1b;
        split2v(a0.x, a0.y, h0a, l0a);
        split2v(a0.z, a0.w, h0b, l0b);
        split2v(a1.x, a1.y, h1a, l1a);
        split2v(a1.z, a1.w, h1b, l1b);
        *(__nv_bfloat162*)&yh[base0] = h0a;
        *(__nv_bfloat162*)&yh[base0 + 2] = h0b;
        *(__nv_bfloat162*)&yl[base0] = l0a;
        *(__nv_bfloat162*)&yl[base0 + 2] = l0b;
        *(__nv_bfloat162*)&yh[base1] = h1a;
        *(__nv_bfloat162*)&yh[base1 + 2] = h1b;
        *(__nv_bfloat162*)&yl[base1] = l1a;
        *(__nv_bfloat162*)&yl[base1 + 2] = l1b;
    }
}

// ---------------- launch ----------------
extern "C" void kernel_launch(void* const* d_in, const int* in_sizes, int n_in,
                              void* d_out, int out_size) {
    (void)in_sizes; (void)n_in; (void)out_size;
    const float* x_anc = (const float*)d_in[0];
    const float* x_nei = (const float*)d_in[1];
    const float* W_q   = (const float*)d_in[2];
    const float* W_k   = (const float*)d_in[3];
    const float* W_v   = (const float*)d_in[4];
    const float* W_o   = (const float*)d_in[5];
    const float* ln1_g = (const float*)d_in[6];
    const float* ln1_b = (const float*)d_in[7];
    const float* ln2_g = (const float*)d_in[8];
    const float* ln2_b = (const float*)d_in[9];
    const float* ff1_w = (const float*)d_in[10];
    const float* ff1_b = (const float*)d_in[11];
    const float* ff2_w = (const float*)d_in[12];
    const float* ff2_b = (const float*)d_in[13];
    float* out = (float*)d_out;

    __nv_bfloat16 *p_xln, *p_Qa, *p_ya, *p_va, *p_hln, *p_acta;
    float *p_Qt, *p_x;
    cudaGetSymbolAddress((void**)&p_xln, a_xln);
    cudaGetSymbolAddress((void**)&p_Qa, a_Q);
    cudaGetSymbolAddress((void**)&p_ya, a_y);
    cudaGetSymbolAddress((void**)&p_va, a_v);
    cudaGetSymbolAddress((void**)&p_hln, a_hln);
    cudaGetSymbolAddress((void**)&p_acta, a_act);
    cudaGetSymbolAddress((void**)&p_Qt, g_Qt);
    cudaGetSymbolAddress((void**)&p_x, g_x);

    __nv_bfloat16 *p_WqT, *p_Wk, *p_WvT, *p_WoT, *p_f1T, *p_f2T;
    cudaGetSymbolAddress((void**)&p_WqT, s_WqT);
    cudaGetSymbolAddress((void**)&p_Wk, s_Wk);
    cudaGetSymbolAddress((void**)&p_WvT, s_WvT);
    cudaGetSymbolAddress((void**)&p_WoT, s_WoT);
    cudaGetSymbolAddress((void**)&p_f1T, s_f1T);
    cudaGetSymbolAddress((void**)&p_f2T, s_f2T);
    const int WD = DD * DD;
    const int WF = DD * FFD;

    const float inv_sqrt_dk = 0.17677669529663687f;  // 1/sqrt(32)
    dim3 tb(32, 8);

    // 0) weight prep
    splitT2<<<dim3(8, 8), tb>>>(W_q, p_WqT, p_WqT + WD, 256, 256);
    splitN<<<256, 256>>>(W_k, p_Wk, p_Wk + WD);
    splitT2<<<dim3(8, 8), tb>>>(W_v, p_WvT, p_WvT + WD, 256, 256);
    splitT2<<<dim3(8, 8), tb>>>(W_o, p_WoT, p_WoT + WD, 256, 256);
    splitT2<<<dim3(32, 8), tb>>>(ff1_w, p_f1T, p_f1T + WF, 256, 1024);
    splitT2<<<dim3(8, 32), tb>>>(ff2_w, p_f2T, p_f2T + WF, 1024, 256);

    // 1) LN1 -> split planes
    ln_split<<<BB / 8, 256>>>(x_anc, ln1_g, ln1_b, p_xln, p_xln + AP);
    // 2) Q = xln @ W_q -> split planes
    mma_gemm2<64, 32, 32, 0, 1><<<dim3(4, 256, 1), 256>>>(
        p_xln, p_xln + AP, 256, 0, p_WqT, p_WqT + WD, 256, 0,
        nullptr, p_Qa, p_Qa + AP, 256, 0, 256, 1.0f, nullptr, nullptr, 0);
    // 3) Qt_h = (Q_h @ Wk_h^T)/sqrt(dk) -> fp32   (A: Q cols h*32.., B: W_k rows)
    mma_gemm2<64, 32, 32, 0, 0><<<dim3(4, 256, 8), 256>>>(
        p_Qa, p_Qa + AP, 256, 32, p_Wk, p_Wk + WD, 256, 32,
        p_Qt, nullptr, nullptr, 2048, 256, 32, inv_sqrt_dk, nullptr, nullptr, 0);
    // 4) attention -> y split planes
    attn_kernel<<<BB, 256>>>(x_nei, p_Qt, p_ya, p_ya + YP);
    // 5) v_h = y_h @ Wv_h -> split planes
    mma_gemm2<32, 32, 16, 0, 1><<<dim3(1, 256, 8), 256>>>(
        p_ya, p_ya + YP, 2048, 256, p_WvT, p_WvT + WD, 256, 32 * 256,
        nullptr, p_va, p_va + AP, 256, 32, 256, 1.0f, nullptr, nullptr, 0);
    // 6) x = x_anc + v @ W_o -> fp32
    mma_gemm2<64, 32, 32, 3, 0><<<dim3(4, 256, 1), 256>>>(
        p_va, p_va + AP, 256, 0, p_WoT, p_WoT + WD, 256, 0,
        p_x, nullptr, nullptr, 256, 0, 256, 1.0f, nullptr, x_anc, 256);
    // 7) LN2 -> split planes
    ln_split<<<BB / 8, 256>>>(p_x, ln2_g, ln2_b, p_hln, p_hln + AP);
    // 8) act = gelu(hln @ ff1_w + ff1_b) -> split planes
    mma_gemm2<64, 32, 32, 1, 1><<<dim3(16, 256, 1), 256>>>(
        p_hln, p_hln + AP, 256, 0, p_f1T, p_f1T + WF, 256, 0,
        nullptr, p_acta, p_acta + FP, 1024, 0, 256, 1.0f, ff1_b, nullptr, 0);
    // 9) out = x + act @ ff2_w + ff2_b -> fp32
    mma_gemm2<64, 32, 32, 2, 0><<<dim3(4, 256, 1), 256>>>(
        p_acta, p_acta + FP, 1024, 0, p_f2T, p_f2T + WF, 1024, 0,
        out, nullptr, nullptr, 256, 0, 1024, 1.0f, ff2_b, p_x, 256);
}